// round 7
// baseline (speedup 1.0000x reference)
#include <cuda_runtime.h>
#include <math.h>

#define HH   256
#define NHH  8
#define HDD  32
#define CC   100
#define NMAX 262144
#define BY   6            // partial blocks per commit in k_main

typedef unsigned long long ull;

// ---------------- device scratch ----------------
__device__ __align__(16) float g_wqk[NHH * HH];
__device__ float g_qb[NHH];
__device__ int   g_counts[CC];
__device__ int   g_offsets[CC + 1];
__device__ int   g_cursor[CC];
__device__ int   g_sorted[NMAX];
__device__ __align__(16) float g_Apart[CC * BY * NHH * HH];   // ~4.9MB partials
__device__ float g_denpart[CC * BY * NHH];
__device__ __align__(16) float g_x[CC * HH];
__device__ __align__(16) float g_qkv[CC * 3 * HH];
__device__ __align__(16) float g_ff[CC * 4 * HH];

// ---------------- helpers ----------------
__device__ __forceinline__ ull fma2(ull a, ull b, ull c) {
    ull d;
    asm("fma.rn.f32x2 %0, %1, %2, %3;" : "=l"(d) : "l"(a), "l"(b), "l"(c));
    return d;
}
__device__ __forceinline__ ull pk2(float lo, float hi) {
    ull r; asm("mov.b64 %0, {%1, %2};" : "=l"(r) : "f"(lo), "f"(hi)); return r;
}
__device__ __forceinline__ void upk2(ull v, float& lo, float& hi) {
    asm("mov.b64 {%0, %1}, %2;" : "=f"(lo), "=f"(hi) : "l"(v));
}

__device__ __forceinline__ float block_ln_256(float v, float gg, float bb, float* red) {
    int t = threadIdx.x, lane = t & 31, w = t >> 5;
    float s = v, q = v * v;
#pragma unroll
    for (int off = 16; off > 0; off >>= 1) {
        s += __shfl_xor_sync(0xffffffffu, s, off);
        q += __shfl_xor_sync(0xffffffffu, q, off);
    }
    if (lane == 0) { red[w] = s; red[8 + w] = q; }
    __syncthreads();
    float S = 0.f, Q = 0.f;
#pragma unroll
    for (int i = 0; i < 8; i++) { S += red[i]; Q += red[8 + i]; }
    float mu  = S * (1.0f / 256.0f);
    float var = Q * (1.0f / 256.0f) - mu * mu;
    return (v - mu) * rsqrtf(var + 1e-5f) * gg + bb;
}

__device__ __forceinline__ float gelu_exact(float v) {
    return 0.5f * v * (1.0f + erff(v * 0.70710678118654752f));
}

// ---------------- setup: wqk precompute + counter init (fused) ----------------
__global__ void k_wqk_init(const float* __restrict__ q, const float* __restrict__ kw,
                           const float* __restrict__ kb) {
    if (blockIdx.x == 8) {
        int t = threadIdx.x;
        if (t < CC) { g_counts[t] = 0; g_cursor[t] = 0; }
        return;
    }
    const float scale = 0.17677669529663687f;
    int h = blockIdx.x, i = threadIdx.x;
    float acc = 0.f;
#pragma unroll 8
    for (int d = 0; d < HDD; d++) acc += q[h * HDD + d] * kw[(h * HDD + d) * HH + i];
    g_wqk[h * HH + i] = acc * scale;
    if (i == 0) {
        float b = 0.f;
        for (int d = 0; d < HDD; d++) b += q[h * HDD + d] * kb[h * HDD + d];
        g_qb[h] = b * scale;
    }
}

// histogram: int4 loads, per-warp sub-histograms
__global__ void __launch_bounds__(256) k_hist(const int* __restrict__ ci, int n) {
    __shared__ int sh[8][CC];
    int t = threadIdx.x, warp = t >> 5;
    for (int j = t; j < 8 * CC; j += 256) sh[j / CC][j % CC] = 0;
    __syncthreads();
    int n4 = n >> 2;
    const int4* ci4 = (const int4*)ci;
    for (int i = blockIdx.x * 256 + t; i < n4; i += gridDim.x * 256) {
        int4 v = ci4[i];
        atomicAdd(&sh[warp][v.x], 1);
        atomicAdd(&sh[warp][v.y], 1);
        atomicAdd(&sh[warp][v.z], 1);
        atomicAdd(&sh[warp][v.w], 1);
    }
    __syncthreads();
    for (int c = t; c < CC; c += 256) {
        int s = 0;
#pragma unroll
        for (int w = 0; w < 8; w++) s += sh[w][c];
        atomicAdd(&g_counts[c], s);
    }
}

// per-block count + scan + range reservation + local scatter
__global__ void __launch_bounds__(256) k_scatter(const int* __restrict__ ci, int n) {
    __shared__ int soff[CC + 1], scnt[CC], sbase[CC], scur[CC];
    int t = threadIdx.x;
    for (int j = t; j < CC; j += 256) { scnt[j] = 0; scur[j] = 0; }
    __syncthreads();
    int per = ((n + gridDim.x - 1) / gridDim.x + 3) & ~3;
    int lo = blockIdx.x * per;
    int hi = min(n, lo + per);
    const int4* ci4 = (const int4*)ci;
    for (int i4 = (lo >> 2) + t; i4 < (hi >> 2); i4 += 256) {
        int4 v = ci4[i4];
        atomicAdd(&scnt[v.x], 1);
        atomicAdd(&scnt[v.y], 1);
        atomicAdd(&scnt[v.z], 1);
        atomicAdd(&scnt[v.w], 1);
    }
    __syncthreads();
    if (t == 0) {
        int s = 0;
        for (int c = 0; c < CC; c++) { soff[c] = s; s += g_counts[c]; }
        soff[CC] = s;
        if (blockIdx.x == 0)
            for (int c = 0; c <= CC; c++) g_offsets[c] = soff[c];
    }
    __syncthreads();
    if (t < CC) sbase[t] = soff[t] + atomicAdd(&g_cursor[t], scnt[t]);
    __syncthreads();
    for (int i = lo + t; i < hi; i += 256) {
        int c = ci[i];
        int p = sbase[c] + atomicAdd(&scur[c], 1);
        g_sorted[p] = i;
    }
}

// ---------------- main streaming pass ----------------
__device__ __forceinline__ void ldrow(ull dst[4], const float* __restrict__ X,
                                      int idx, int lane) {
    const ull* r = (const ull*)(X + (size_t)idx * 256);
    dst[0] = __ldcs(r + lane);
    dst[1] = __ldcs(r + 32 + lane);
    dst[2] = __ldcs(r + 64 + lane);
    dst[3] = __ldcs(r + 96 + lane);
}

__device__ __forceinline__ void mainstep(const ull x[4], const ull w2[8][4],
                                         const float qbv[8], ull a2[8][4],
                                         float dacc[8]) {
    float p[8];
#pragma unroll
    for (int h = 0; h < 8; h++) {
        ull acc = fma2(x[0], w2[h][0], 0ull);
        acc = fma2(x[1], w2[h][1], acc);
        acc = fma2(x[2], w2[h][2], acc);
        acc = fma2(x[3], w2[h][3], acc);
        float lo, hi; upk2(acc, lo, hi);
        p[h] = lo + hi;
    }
#pragma unroll
    for (int off = 16; off > 0; off >>= 1)
#pragma unroll
        for (int h = 0; h < 8; h++)
            p[h] += __shfl_xor_sync(0xffffffffu, p[h], off);
#pragma unroll
    for (int h = 0; h < 8; h++) {
        float e = __expf(p[h] + qbv[h]);
        dacc[h] += e;
        ull e2 = pk2(e, e);
        a2[h][0] = fma2(e2, x[0], a2[h][0]);
        a2[h][1] = fma2(e2, x[1], a2[h][1]);
        a2[h][2] = fma2(e2, x[2], a2[h][2]);
        a2[h][3] = fma2(e2, x[3], a2[h][3]);
    }
}

// grid (CC, BY), 128 threads (4 warps). 2 CTAs/SM. Ping-pong buffers, no copies,
// indices prefetched 2 nodes ahead.
__global__ void __launch_bounds__(128) k_main(const float* __restrict__ X) {
    __shared__ ull sred[2][1024];
    __shared__ float sden[4][8];
    int c = blockIdx.x;
    int warp = threadIdx.x >> 5;
    int lane = threadIdx.x & 31;
    int wg = blockIdx.y * 4 + warp;        // 0..23
    const int S = BY * 4;                  // 24
    int start = g_offsets[c], end = g_offsets[c + 1];

    ull w2[8][4];
    float qbv[8];
#pragma unroll
    for (int h = 0; h < 8; h++) {
        qbv[h] = g_qb[h];
#pragma unroll
        for (int k = 0; k < 4; k++)
            w2[h][k] = *(const ull*)(g_wqk + h * 256 + k * 64 + 2 * lane);
    }
    ull a2[8][4];
#pragma unroll
    for (int h = 0; h < 8; h++)
#pragma unroll
        for (int k = 0; k < 4; k++) a2[h][k] = 0ull;
    float dacc[8];
#pragma unroll
    for (int h = 0; h < 8; h++) dacc[h] = 0.f;

    int i = start + wg;
    int safe = (i < end) ? g_sorted[i] : 0;
    int id0 = safe;
    int id1 = (i + S     < end) ? g_sorted[i + S]     : safe;
    int pE  = i + 2 * S;
    int pO  = i + 3 * S;
    int idE = (pE < end) ? g_sorted[pE] : safe;
    int idO = (pO < end) ? g_sorted[pO] : safe;

    ull bA[4], bB[4];
    ldrow(bA, X, id0, lane);
    ldrow(bB, X, id1, lane);

    while (i < end) {
        mainstep(bA, w2, qbv, a2, dacc);
        ldrow(bA, X, idE, lane);              // row for i+2S (addr ready)
        pE += 2 * S;
        idE = (pE < end) ? g_sorted[pE] : safe;
        i += S;
        if (i >= end) break;
        mainstep(bB, w2, qbv, a2, dacc);
        ldrow(bB, X, idO, lane);              // row for i+2S (odd slot)
        pO += 2 * S;
        idO = (pO < end) ? g_sorted[pO] : safe;
        i += S;
    }

    if (lane == 0)
#pragma unroll
        for (int h = 0; h < 8; h++) sden[warp][h] = dacc[h];

    // tree reduce 4 warps -> 1
    if (warp >= 2)
#pragma unroll
        for (int h = 0; h < 8; h++)
#pragma unroll
            for (int k = 0; k < 4; k++)
                sred[warp - 2][h * 128 + k * 32 + lane] = a2[h][k];
    __syncthreads();
    if (warp < 2)
#pragma unroll
        for (int h = 0; h < 8; h++)
#pragma unroll
            for (int k = 0; k < 4; k++) {
                float alo, ahi, blo, bhi;
                upk2(a2[h][k], alo, ahi);
                upk2(sred[warp][h * 128 + k * 32 + lane], blo, bhi);
                a2[h][k] = pk2(alo + blo, ahi + bhi);
            }
    __syncthreads();
    if (warp == 1)
#pragma unroll
        for (int h = 0; h < 8; h++)
#pragma unroll
            for (int k = 0; k < 4; k++)
                sred[0][h * 128 + k * 32 + lane] = a2[h][k];
    __syncthreads();
    if (warp == 0) {
        ull* dst = (ull*)(g_Apart + (size_t)(c * BY + blockIdx.y) * 2048);
#pragma unroll
        for (int h = 0; h < 8; h++)
#pragma unroll
            for (int k = 0; k < 4; k++) {
                float alo, ahi, blo, bhi;
                upk2(a2[h][k], alo, ahi);
                upk2(sred[0][h * 128 + k * 32 + lane], blo, bhi);
                dst[h * 128 + k * 32 + lane] = pk2(alo + blo, ahi + bhi);
            }
        if (lane < 8) {
            float d = 0.f;
#pragma unroll
            for (int w = 0; w < 4; w++) d += sden[w][lane];
            g_denpart[(c * BY + blockIdx.y) * 8 + lane] = d;
        }
    }
}

// pooled = (A·v_w^T)/den + v_b; emb = LN(pooled @ po_w^T + po_b); gate empty commits.
__global__ void __launch_bounds__(256) k_pool(const float* __restrict__ vw,
                                              const float* __restrict__ vb,
                                              const float* __restrict__ pw,
                                              const float* __restrict__ pb,
                                              const float* __restrict__ png,
                                              const float* __restrict__ pnb) {
    int c = blockIdx.x, t = threadIdx.x, warp = t >> 5, lane = t & 31;
    __shared__ __align__(16) float shA[2048];
    __shared__ __align__(16) float shP[256];
    __shared__ float shO[256];
    __shared__ float shden[8];
    __shared__ float red[16];
#pragma unroll
    for (int j = 0; j < 8; j++) {
        float s = 0.f;
#pragma unroll
        for (int p = 0; p < BY; p++)
            s += g_Apart[(size_t)(c * BY + p) * 2048 + t + 256 * j];
        shA[t + 256 * j] = s;
    }
    if (t < 8) {
        float d = 0.f;
#pragma unroll
        for (int p = 0; p < BY; p++) d += g_denpart[(c * BY + p) * 8 + t];
        shden[t] = d;
    }
    __syncthreads();
    int h = warp;
    float den = shden[h];
    float rden = den > 0.f ? 1.f / den : 0.f;
    for (int d = 0; d < 32; d++) {
        const float* w = vw + (h * 32 + d) * 256;
        float4 wa = *(const float4*)(w + 4 * lane);
        float4 wb = *(const float4*)(w + 128 + 4 * lane);
        float4 xa = *(const float4*)(shA + h * 256 + 4 * lane);
        float4 xb = *(const float4*)(shA + h * 256 + 128 + 4 * lane);
        float s = wa.x * xa.x + wa.y * xa.y + wa.z * xa.z + wa.w * xa.w
                + wb.x * xb.x + wb.y * xb.y + wb.z * xb.z + wb.w * xb.w;
#pragma unroll
        for (int off = 16; off > 0; off >>= 1) s += __shfl_xor_sync(0xffffffffu, s, off);
        if (lane == 0)
            shP[h * 32 + d] = (den > 0.f) ? (s * rden + vb[h * 32 + d]) : 0.f;
    }
    __syncthreads();
    for (int d = 0; d < 32; d++) {
        int j = warp * 32 + d;
        const float* w = pw + j * 256;
        float4 wa = *(const float4*)(w + 4 * lane);
        float4 wb = *(const float4*)(w + 128 + 4 * lane);
        float4 xa = *(const float4*)(shP + 4 * lane);
        float4 xb = *(const float4*)(shP + 128 + 4 * lane);
        float s = wa.x * xa.x + wa.y * xa.y + wa.z * xa.z + wa.w * xa.w
                + wb.x * xb.x + wb.y * xb.y + wb.z * xb.z + wb.w * xb.w;
#pragma unroll
        for (int off = 16; off > 0; off >>= 1) s += __shfl_xor_sync(0xffffffffu, s, off);
        if (lane == 0) shO[j] = s + pb[j];
    }
    __syncthreads();
    float r = block_ln_256(shO[t], png[t], pnb[t], red);
    g_x[c * 256 + t] = (g_counts[c] > 0) ? r : 0.f;
}

// qkv projection, 4 commits per block, 256-row slice per blockIdx.y (3 slices).
__global__ void __launch_bounds__(256) k_qkv(const float* __restrict__ W,
                                             const float* __restrict__ B) {
    int cbase = blockIdx.x * 4, t = threadIdx.x, warp = t >> 5, lane = t & 31;
    int jbase = blockIdx.y * 256;
    __shared__ __align__(16) float shx[4][256];
#pragma unroll
    for (int cc = 0; cc < 4; cc++)
        shx[cc][t] = g_x[(cbase + cc) * 256 + t];
    __syncthreads();
    for (int r = 0; r < 32; r++) {
        int j = jbase + warp * 32 + r;
        const float* w = W + (size_t)j * 256;
        float4 wa = *(const float4*)(w + 4 * lane);
        float4 wb = *(const float4*)(w + 128 + 4 * lane);
        float s[4];
#pragma unroll
        for (int cc = 0; cc < 4; cc++) {
            float4 xa = *(const float4*)(&shx[cc][4 * lane]);
            float4 xb = *(const float4*)(&shx[cc][128 + 4 * lane]);
            s[cc] = wa.x * xa.x + wa.y * xa.y + wa.z * xa.z + wa.w * xa.w
                  + wb.x * xb.x + wb.y * xb.y + wb.z * xb.z + wb.w * xb.w;
        }
#pragma unroll
        for (int off = 16; off > 0; off >>= 1)
#pragma unroll
            for (int cc = 0; cc < 4; cc++)
                s[cc] += __shfl_xor_sync(0xffffffffu, s[cc], off);
        if (lane == 0) {
            float bj = B[j];
#pragma unroll
            for (int cc = 0; cc < 4; cc++)
                g_qkv[(cbase + cc) * 768 + j] = s[cc] + bj;
        }
    }
}

// attention over commits + output projection + residual + LN, fused per-commit.
__global__ void __launch_bounds__(256) k_attn_oln(const float* __restrict__ W,
                                                  const float* __restrict__ B,
                                                  const float* __restrict__ gg,
                                                  const float* __restrict__ bb) {
    int c = blockIdx.x, t = threadIdx.x, h = t >> 5, lane = t & 31;
    __shared__ __align__(16) float shq[256];
    __shared__ float she[8][128];
    __shared__ float satt[256];
    __shared__ float sho[256];
    __shared__ float red[16];
    shq[t] = g_qkv[c * 768 + t];
    __syncthreads();
    const float scale = 0.17677669529663687f;
    float sc[4];
#pragma unroll
    for (int r = 0; r < 4; r++) {
        int m = lane + 32 * r;
        if (m < CC) {
            const float* kk = g_qkv + m * 768 + 256 + h * 32;
            const float* qq = shq + h * 32;
            float s = 0.f;
#pragma unroll
            for (int kx = 0; kx < 8; kx++) {
                float4 a = *(const float4*)(kk + 4 * kx);
                float4 b = *(const float4*)(qq + 4 * kx);
                s += a.x * b.x + a.y * b.y + a.z * b.z + a.w * b.w;
            }
            sc[r] = s * scale;
        } else sc[r] = -3.0e38f;
    }
    float M = fmaxf(fmaxf(sc[0], sc[1]), fmaxf(sc[2], sc[3]));
#pragma unroll
    for (int off = 16; off > 0; off >>= 1) M = fmaxf(M, __shfl_xor_sync(0xffffffffu, M, off));
    float sum = 0.f;
#pragma unroll
    for (int r = 0; r < 4; r++) {
        int m = lane + 32 * r;
        float e = (m < CC) ? __expf(sc[r] - M) : 0.f;
        if (m < CC) she[h][m] = e;
        sum += e;
    }
#pragma unroll
    for (int off = 16; off > 0; off >>= 1) sum += __shfl_xor_sync(0xffffffffu, sum, off);
    __syncwarp();
    float inv = 1.f / sum;
    float acc = 0.f;
#pragma unroll 4
    for (int m = 0; m < CC; m++)
        acc += she[h][m] * g_qkv[m * 768 + 512 + h * 32 + lane];
    satt[h * 32 + lane] = acc * inv;
    __syncthreads();
    for (int d = 0; d < 32; d++) {
        int j = h * 32 + d;
        const float* w = W + (size_t)j * 256;
        float4 wa = *(const float4*)(w + 4 * lane);
        float4 wb = *(const float4*)(w + 128 + 4 * lane);
        float4 xa = *(const float4*)(satt + 4 * lane);
        float4 xb = *(const float4*)(satt + 128 + 4 * lane);
        float s = wa.x * xa.x + wa.y * xa.y + wa.z * xa.z + wa.w * xa.w
                + wb.x * xb.x + wb.y * xb.y + wb.z * xb.z + wb.w * xb.w;
#pragma unroll
        for (int off = 16; off > 0; off >>= 1) s += __shfl_xor_sync(0xffffffffu, s, off);
        if (lane == 0) sho[j] = s;
    }
    __syncthreads();
    float v = g_x[c * 256 + t] + sho[t] + B[t];
    float r = block_ln_256(v, gg[t], bb[t], red);
    g_x[c * 256 + t] = r;
}

// ff1 + gelu, 4 commits per block, 256-row slice per blockIdx.y (4 slices).
__global__ void __launch_bounds__(256) k_ff1(const float* __restrict__ W,
                                             const float* __restrict__ B) {
    int cbase = blockIdx.x * 4, t = threadIdx.x, warp = t >> 5, lane = t & 31;
    int jbase = blockIdx.y * 256;
    __shared__ __align__(16) float shx[4][256];
#pragma unroll
    for (int cc = 0; cc < 4; cc++)
        shx[cc][t] = g_x[(cbase + cc) * 256 + t];
    __syncthreads();
    for (int r = 0; r < 32; r++) {
        int j = jbase + warp * 32 + r;
        const float* w = W + (size_t)j * 256;
        float4 wa = *(const float4*)(w + 4 * lane);
        float4 wb = *(const float4*)(w + 128 + 4 * lane);
        float s[4];
#pragma unroll
        for (int cc = 0; cc < 4; cc++) {
            float4 xa = *(const float4*)(&shx[cc][4 * lane]);
            float4 xb = *(const float4*)(&shx[cc][128 + 4 * lane]);
            s[cc] = wa.x * xa.x + wa.y * xa.y + wa.z * xa.z + wa.w * xa.w
                  + wb.x * xb.x + wb.y * xb.y + wb.z * xb.z + wb.w * xb.w;
        }
#pragma unroll
        for (int off = 16; off > 0; off >>= 1)
#pragma unroll
            for (int cc = 0; cc < 4; cc++)
                s[cc] += __shfl_xor_sync(0xffffffffu, s[cc], off);
        if (lane == 0) {
            float bj = B[j];
#pragma unroll
            for (int cc = 0; cc < 4; cc++)
                g_ff[(cbase + cc) * 1024 + j] = gelu_exact(s[cc] + bj);
        }
    }
}

// ff2 + residual + LN, 4 commits per block; optionally fused ranking head.
__global__ void __launch_bounds__(256) k_ff2(const float* __restrict__ W,
                                             const float* __restrict__ B,
                                             const float* __restrict__ gg,
                                             const float* __restrict__ bb,
                                             int final_layer,
                                             const float* __restrict__ r1w,
                                             const float* __restrict__ r1b,
                                             const float* __restrict__ r2w,
                                             const float* __restrict__ r2b,
                                             float* __restrict__ out) {
    int cbase = blockIdx.x * 4, t = threadIdx.x, warp = t >> 5, lane = t & 31;
    __shared__ __align__(16) float shf[4][1024];
    __shared__ float sho[4][256];
    __shared__ float red[16];
    __shared__ __align__(16) float shx[4][256];
    __shared__ float shh[4][128];
#pragma unroll
    for (int cc = 0; cc < 4; cc++)
        for (int idx = t; idx < 1024; idx += 256)
            shf[cc][idx] = g_ff[(cbase + cc) * 1024 + idx];
    __syncthreads();
    for (int r = 0; r < 32; r++) {
        int j = warp * 32 + r;
        const float4* wr = (const float4*)(W + (size_t)j * 1024);
        float4 wreg[8];
#pragma unroll
        for (int q = 0; q < 8; q++) wreg[q] = wr[q * 32 + lane];
        float s[4];
#pragma unroll
        for (int cc = 0; cc < 4; cc++) {
            float acc = 0.f;
#pragma unroll
            for (int q = 0; q < 8; q++) {
                float4 x = *(const float4*)(&shf[cc][q * 128 + 4 * lane]);
                acc += wreg[q].x * x.x + wreg[q].y * x.y + wreg[q].z * x.z + wreg[q].w * x.w;
            }
            s[cc] = acc;
        }
#pragma unroll
        for (int off = 16; off > 0; off >>= 1)
#pragma unroll
            for (int cc = 0; cc < 4; cc++)
                s[cc] += __shfl_xor_sync(0xffffffffu, s[cc], off);
        if (lane == 0) {
            float bj = B[j];
#pragma unroll
            for (int cc = 0; cc < 4; cc++) sho[cc][j] = s[cc] + bj;
        }
    }
    __syncthreads();
#pragma unroll
    for (int cc = 0; cc < 4; cc++) {
        int c = cbase + cc;
        float v = g_x[c * 256 + t] + sho[cc][t];
        float r = block_ln_256(v, gg[t], bb[t], red);
        if (final_layer) shx[cc][t] = r;
        else g_x[c * 256 + t] = r;
        __syncthreads();
    }
    if (!final_layer) return;

    // ---- fused ranking head ----
    for (int r = 0; r < 16; r++) {
        int j = warp * 16 + r;
        const float* w = r1w + (size_t)j * 256;
        float4 wa = *(const float4*)(w + 4 * lane);
        float4 wb = *(const float4*)(w + 128 + 4 * lane);
        float s[4];
#pragma unroll
        for (int cc = 0; cc < 4; cc++) {
            float4 xa = *(const float4*)(&shx[cc][4 * lane]);
            float4 xb = *(const float4*)(&shx[cc][128 + 4 * lane]);
            s[cc] = wa.x * xa.x + wa.y * xa.y + wa.z * xa.z + wa.w * xa.w
                  + wb.x * xb.x + wb.y * xb.y + wb.z * xb.z + wb.w * xb.w;
        }
#pragma unroll
        for (int off = 16; off > 0; off >>= 1)
#pragma unroll
            for (int cc = 0; cc < 4; cc++)
                s[cc] += __shfl_xor_sync(0xffffffffu, s[cc], off);
        if (lane == 0) {
            float bj = r1b[j];
#pragma unroll
            for (int cc = 0; cc < 4; cc++)
                shh[cc][j] = gelu_exact(s[cc] + bj);
        }
    }
    __syncthreads();
    if (warp < 4) {
        float s = 0.f;
#pragma unroll
        for (int r = 0; r < 4; r++)
            s += shh[warp][lane + 32 * r] * r2w[lane + 32 * r];
#pragma unroll
        for (int off = 16; off > 0; off >>= 1) s += __shfl_xor_sync(0xffffffffu, s, off);
        if (lane == 0) out[cbase + warp] = s + r2b[0];
    }
}

// ---------------- launch ----------------
extern "C" void kernel_launch(void* const* d_in, const int* in_sizes, int n_in,
                              void* d_out, int out_size) {
    const float* x    = (const float*)d_in[0];
    const int*   ci   = (const int*)d_in[1];
    const float* q    = (const float*)d_in[3];
    const float* kw   = (const float*)d_in[4];
    const float* kb   = (const float*)d_in[5];
    const float* vw   = (const float*)d_in[6];
    const float* vb   = (const float*)d_in[7];
    const float* pw   = (const float*)d_in[8];
    const float* pb   = (const float*)d_in[9];
    const float* png  = (const float*)d_in[10];
    const float* pnb  = (const float*)d_in[11];
    const float* tinw = (const float*)d_in[12];
    const float* tinb = (const float*)d_in[13];
    const float* totw = (const float*)d_in[14];
    const float* totb = (const float*)d_in[15];
    const float* ln1g = (const float*)d_in[16];
    const float* ln1b = (const float*)d_in[17];
    const float* ff1w = (const float*)d_in[18];
    const float* ff1b = (const float*)d_in[19];
    const float* ff2w = (const float*)d_in[20];
    const float* ff2b = (const float*)d_in[21];
    const float* ln2g = (const float*)d_in[22];
    const float* ln2b = (const float*)d_in[23];
    const float* r1w  = (const float*)d_in[24];
    const float* r1b  = (const float*)d_in[25];
    const float* r2w  = (const float*)d_in[26];
    const float* r2b  = (const float*)d_in[27];
    float* out = (float*)d_out;
    int n = in_sizes[0] / HH;

    k_wqk_init<<<9, 256>>>(q, kw, kb);        // launch 1
    k_hist<<<256, 256>>>(ci, n);              // launch 2
    k_scatter<<<256, 256>>>(ci, n);           // launch 3
    k_main<<<dim3(CC, BY), 128>>>(x);         // launch 4  (profiled)
    k_pool<<<CC, 256>>>(vw, vb, pw, pb, png, pnb);
    for (int l = 0; l < 2; l++) {
        k_qkv<<<dim3(25, 3), 256>>>(tinw + (size_t)l * 768 * 256, tinb + l * 768);
        k_attn_oln<<<CC, 256>>>(totw + (size_t)l * 256 * 256, totb + l * 256,
                                ln1g + l * 256, ln1b + l * 256);
        k_ff1<<<dim3(25, 4), 256>>>(ff1w + (size_t)l * 1024 * 256, ff1b + l * 1024);
        k_ff2<<<25, 256>>>(ff2w + (size_t)l * 256 * 1024, ff2b + l * 256,
                           ln2g + l * 256, ln2b + l * 256,
                           (l == 1) ? 1 : 0, r1w, r1b, r2w, r2b, out);
    }
}

// round 12
// speedup vs baseline: 1.0842x; 1.0842x over previous
#include <cuda_runtime.h>
#include <math.h>

#define HH   256
#define NHH  8
#define CC   100
#define NMAX 262144
#define BY   9            // partial chunks per commit in k_main
#define TW   8            // nodes per shared tile in k_main

typedef unsigned long long ull;

// ---------------- device scratch ----------------
__device__ __align__(16) float g_wqk[NHH * HH];
__device__ int   g_counts[CC];
__device__ int   g_offsets[CC + 1];
__device__ int   g_cursor[CC];
__device__ int   g_sorted[NMAX];
__device__ __align__(16) float g_Apart[CC * BY * NHH * HH];   // ~7.4MB partials
__device__ float g_denpart[CC * BY * NHH];
__device__ __align__(16) float g_x[CC * HH];
__device__ __align__(16) float g_qkvA[CC * 3 * HH];
__device__ __align__(16) float g_qkvB[CC * 3 * HH];

// ---------------- helpers ----------------
__device__ __forceinline__ ull fma2(ull a, ull b, ull c) {
    ull d;
    asm("fma.rn.f32x2 %0, %1, %2, %3;" : "=l"(d) : "l"(a), "l"(b), "l"(c));
    return d;
}
__device__ __forceinline__ void upk2(ull v, float& lo, float& hi) {
    asm("mov.b64 {%0, %1}, %2;" : "=f"(lo), "=f"(hi) : "l"(v));
}
__device__ __forceinline__ ull pk2(float lo, float hi) {
    ull r; asm("mov.b64 %0, {%1, %2};" : "=l"(r) : "f"(lo), "f"(hi)); return r;
}
__device__ __forceinline__ float gelu_exact(float v) {
    return 0.5f * v * (1.0f + erff(v * 0.70710678118654752f));
}

// ---------------- setup ----------------
// wqk[h,i] = scale * sum_d q[h,d]*k_w[h*32+d, i]  (bias qb cancels in softmax ratio)
__global__ void k_wqk_init(const float* __restrict__ q, const float* __restrict__ kw) {
    if (blockIdx.x == 8) {
        int t = threadIdx.x;
        if (t < CC) { g_counts[t] = 0; g_cursor[t] = 0; }
        return;
    }
    const float scale = 0.17677669529663687f;
    int h = blockIdx.x, i = threadIdx.x;
    float acc = 0.f;
#pragma unroll 8
    for (int d = 0; d < 32; d++) acc += q[h * 32 + d] * kw[(h * 32 + d) * HH + i];
    g_wqk[h * HH + i] = acc * scale;
}

__global__ void __launch_bounds__(256) k_hist(const int* __restrict__ ci, int n) {
    __shared__ int sh[8][CC];
    int t = threadIdx.x, warp = t >> 5;
    for (int j = t; j < 8 * CC; j += 256) sh[j / CC][j % CC] = 0;
    __syncthreads();
    int n4 = n >> 2;
    const int4* ci4 = (const int4*)ci;
    for (int i = blockIdx.x * 256 + t; i < n4; i += gridDim.x * 256) {
        int4 v = ci4[i];
        atomicAdd(&sh[warp][v.x], 1);
        atomicAdd(&sh[warp][v.y], 1);
        atomicAdd(&sh[warp][v.z], 1);
        atomicAdd(&sh[warp][v.w], 1);
    }
    __syncthreads();
    for (int c = t; c < CC; c += 256) {
        int s = 0;
#pragma unroll
        for (int w = 0; w < 8; w++) s += sh[w][c];
        atomicAdd(&g_counts[c], s);
    }
}

__global__ void __launch_bounds__(256) k_scatter(const int* __restrict__ ci, int n) {
    __shared__ int soff[CC + 1], scnt[CC], sbase[CC], scur[CC];
    int t = threadIdx.x;
    for (int j = t; j < CC; j += 256) { scnt[j] = 0; scur[j] = 0; }
    __syncthreads();
    int per = ((n + gridDim.x - 1) / gridDim.x + 3) & ~3;
    int lo = blockIdx.x * per;
    int hi = min(n, lo + per);
    const int4* ci4 = (const int4*)ci;
    for (int i4 = (lo >> 2) + t; i4 < (hi >> 2); i4 += 256) {
        int4 v = ci4[i4];
        atomicAdd(&scnt[v.x], 1);
        atomicAdd(&scnt[v.y], 1);
        atomicAdd(&scnt[v.z], 1);
        atomicAdd(&scnt[v.w], 1);
    }
    __syncthreads();
    if (t == 0) {
        int s = 0;
        for (int c = 0; c < CC; c++) { soff[c] = s; s += g_counts[c]; }
        soff[CC] = s;
        if (blockIdx.x == 0)
            for (int c = 0; c <= CC; c++) g_offsets[c] = soff[c];
    }
    __syncthreads();
    if (t < CC) sbase[t] = soff[t] + atomicAdd(&g_cursor[t], scnt[t]);
    __syncthreads();
    for (int i = lo + t; i < hi; i += 256) {
        int c = ci[i];
        int p = sbase[c] + atomicAdd(&scur[c], 1);
        g_sorted[p] = i;
    }
}

// ---------------- main streaming pass ----------------
// CTA = 128 threads (4 warps). Warp w owns heads {2w, 2w+1}. Tiles of TW rows
// staged in shared (double buffered). No cross-warp reduce needed.
__global__ void __launch_bounds__(128) k_main(const float* __restrict__ X) {
    __shared__ __align__(16) float tile[2][TW * 256];
    int c = blockIdx.x;
    int t = threadIdx.x;
    int warp = t >> 5, lane = t & 31;
    int start = g_offsets[c], end = g_offsets[c + 1];
    int cnt = end - start;
    int chunk = (cnt + BY - 1) / BY;
    int mylo = start + blockIdx.y * chunk;
    int myhi = min(end, mylo + chunk);
    int nt = myhi - mylo;
    int ntiles = (nt + TW - 1) / TW;

    int h0 = warp * 2;
    ull w2[2][4];
#pragma unroll
    for (int hh = 0; hh < 2; hh++)
#pragma unroll
        for (int k = 0; k < 4; k++)
            w2[hh][k] = *(const ull*)(g_wqk + (h0 + hh) * 256 + k * 64 + 2 * lane);
    ull a2[2][4];
#pragma unroll
    for (int hh = 0; hh < 2; hh++)
#pragma unroll
        for (int k = 0; k < 4; k++) a2[hh][k] = 0ull;
    float dacc[2] = {0.f, 0.f};

    int lr = t >> 4, sub = t & 15;   // load role: 16 threads per row

    if (nt > 0) {
        // load tile 0
        {
            int p = mylo + lr;
            int node = (p < myhi) ? g_sorted[p] : g_sorted[mylo];
            const float4* src = (const float4*)(X + (size_t)node * 256);
            float4* dst = (float4*)(&tile[0][lr * 256]);
            dst[sub]      = __ldcs(src + sub);
            dst[sub + 16] = __ldcs(src + sub + 16);
            dst[sub + 32] = __ldcs(src + sub + 32);
            dst[sub + 48] = __ldcs(src + sub + 48);
        }
        int buf = 0;
        for (int j = 0; j < ntiles; j++) {
            __syncthreads();
            if (j + 1 < ntiles) {
                int p = mylo + (j + 1) * TW + lr;
                int node = (p < myhi) ? g_sorted[p] : g_sorted[mylo];
                const float4* src = (const float4*)(X + (size_t)node * 256);
                float4* dst = (float4*)(&tile[buf ^ 1][lr * 256]);
                dst[sub]      = __ldcs(src + sub);
                dst[sub + 16] = __ldcs(src + sub + 16);
                dst[sub + 32] = __ldcs(src + sub + 32);
                dst[sub + 48] = __ldcs(src + sub + 48);
            }
            int rmax = min(TW, nt - j * TW);
            const float* tb = tile[buf];
            for (int rr = 0; rr < rmax; rr++) {
                const float* row = tb + rr * 256;
                ull x0 = *(const ull*)(row + 2 * lane);
                ull x1 = *(const ull*)(row + 64 + 2 * lane);
                ull x2 = *(const ull*)(row + 128 + 2 * lane);
                ull x3 = *(const ull*)(row + 192 + 2 * lane);
                float p0, p1;
                {
                    ull acc = fma2(x0, w2[0][0], 0ull);
                    acc = fma2(x1, w2[0][1], acc);
                    acc = fma2(x2, w2[0][2], acc);
                    acc = fma2(x3, w2[0][3], acc);
                    float lo, hi; upk2(acc, lo, hi); p0 = lo + hi;
                }
                {
                    ull acc = fma2(x0, w2[1][0], 0ull);
                    acc = fma2(x1, w2[1][1], acc);
                    acc = fma2(x2, w2[1][2], acc);
                    acc = fma2(x3, w2[1][3], acc);
                    float lo, hi; upk2(acc, lo, hi); p1 = lo + hi;
                }
#pragma unroll
                for (int off = 16; off > 0; off >>= 1) {
                    p0 += __shfl_xor_sync(0xffffffffu, p0, off);
                    p1 += __shfl_xor_sync(0xffffffffu, p1, off);
                }
                float e0 = __expf(p0), e1 = __expf(p1);
                dacc[0] += e0; dacc[1] += e1;
                ull e02 = pk2(e0, e0), e12 = pk2(e1, e1);
                a2[0][0] = fma2(e02, x0, a2[0][0]);
                a2[0][1] = fma2(e02, x1, a2[0][1]);
                a2[0][2] = fma2(e02, x2, a2[0][2]);
                a2[0][3] = fma2(e02, x3, a2[0][3]);
                a2[1][0] = fma2(e12, x0, a2[1][0]);
                a2[1][1] = fma2(e12, x1, a2[1][1]);
                a2[1][2] = fma2(e12, x2, a2[1][2]);
                a2[1][3] = fma2(e12, x3, a2[1][3]);
            }
            buf ^= 1;
        }
    }
    // write this chunk's partials (zeros if empty chunk — k_pool sums all BY)
    ull* base = (ull*)(g_Apart + (size_t)(c * BY + blockIdx.y) * 2048);
#pragma unroll
    for (int hh = 0; hh < 2; hh++)
#pragma unroll
        for (int k = 0; k < 4; k++)
            base[(h0 + hh) * 128 + k * 32 + lane] = a2[hh][k];
    if (lane == 0) {
        g_denpart[(c * BY + blockIdx.y) * 8 + h0]     = dacc[0];
        g_denpart[(c * BY + blockIdx.y) * 8 + h0 + 1] = dacc[1];
    }
}

// ---------------- pooling epilogue ----------------
__device__ __forceinline__ float block_ln_256(float v, float gg, float bb, float* red) {
    int t = threadIdx.x, lane = t & 31, w = t >> 5;
    float s = v, q = v * v;
#pragma unroll
    for (int off = 16; off > 0; off >>= 1) {
        s += __shfl_xor_sync(0xffffffffu, s, off);
        q += __shfl_xor_sync(0xffffffffu, q, off);
    }
    if (lane == 0) { red[w] = s; red[8 + w] = q; }
    __syncthreads();
    float S = 0.f, Q = 0.f;
#pragma unroll
    for (int i = 0; i < 8; i++) { S += red[i]; Q += red[8 + i]; }
    float mu  = S * (1.0f / 256.0f);
    float var = Q * (1.0f / 256.0f) - mu * mu;
    return (v - mu) * rsqrtf(var + 1e-5f) * gg + bb;
}

__global__ void __launch_bounds__(256) k_pool(const float* __restrict__ vw,
                                              const float* __restrict__ vb,
                                              const float* __restrict__ pw,
                                              const float* __restrict__ pb,
                                              const float* __restrict__ png,
                                              const float* __restrict__ pnb) {
    int c = blockIdx.x, t = threadIdx.x, warp = t >> 5, lane = t & 31;
    __shared__ __align__(16) float shA[2048];
    __shared__ __align__(16) float shP[256];
    __shared__ float shO[256];
    __shared__ float shden[8];
    __shared__ float red[16];
#pragma unroll
    for (int j = 0; j < 8; j++) {
        float s = 0.f;
#pragma unroll
        for (int p = 0; p < BY; p++)
            s += g_Apart[(size_t)(c * BY + p) * 2048 + t + 256 * j];
        shA[t + 256 * j] = s;
    }
    if (t < 8) {
        float d = 0.f;
#pragma unroll
        for (int p = 0; p < BY; p++) d += g_denpart[(c * BY + p) * 8 + t];
        shden[t] = d;
    }
    __syncthreads();
    int h = warp;
    float den = shden[h];
    float rden = den > 0.f ? 1.f / den : 0.f;
    for (int d = 0; d < 32; d++) {
        const float* w = vw + (h * 32 + d) * 256;
        float4 wa = *(const float4*)(w + 4 * lane);
        float4 wb = *(const float4*)(w + 128 + 4 * lane);
        float4 xa = *(const float4*)(shA + h * 256 + 4 * lane);
        float4 xb = *(const float4*)(shA + h * 256 + 128 + 4 * lane);
        float s = wa.x * xa.x + wa.y * xa.y + wa.z * xa.z + wa.w * xa.w
                + wb.x * xb.x + wb.y * xb.y + wb.z * xb.z + wb.w * xb.w;
#pragma unroll
        for (int off = 16; off > 0; off >>= 1) s += __shfl_xor_sync(0xffffffffu, s, off);
        if (lane == 0)
            shP[h * 32 + d] = (den > 0.f) ? (s * rden + vb[h * 32 + d]) : 0.f;
    }
    __syncthreads();
    for (int d = 0; d < 32; d++) {
        int j = warp * 32 + d;
        const float* w = pw + j * 256;
        float4 wa = *(const float4*)(w + 4 * lane);
        float4 wb = *(const float4*)(w + 128 + 4 * lane);
        float4 xa = *(const float4*)(shP + 4 * lane);
        float4 xb = *(const float4*)(shP + 128 + 4 * lane);
        float s = wa.x * xa.x + wa.y * xa.y + wa.z * xa.z + wa.w * xa.w
                + wb.x * xb.x + wb.y * xb.y + wb.z * xb.z + wb.w * xb.w;
#pragma unroll
        for (int off = 16; off > 0; off >>= 1) s += __shfl_xor_sync(0xffffffffu, s, off);
        if (lane == 0) shO[j] = s + pb[j];
    }
    __syncthreads();
    float r = block_ln_256(shO[t], png[t], pnb[t], red);
    g_x[c * 256 + t] = (g_counts[c] > 0) ? r : 0.f;
}

// qkv projection for layer 0: 4 commits per block, 256-row slice per blockIdx.y.
__global__ void __launch_bounds__(256) k_qkv(const float* __restrict__ W,
                                             const float* __restrict__ B) {
    int cbase = blockIdx.x * 4, t = threadIdx.x, warp = t >> 5, lane = t & 31;
    int jbase = blockIdx.y * 256;
    __shared__ __align__(16) float shx[4][256];
#pragma unroll
    for (int cc = 0; cc < 4; cc++)
        shx[cc][t] = g_x[(cbase + cc) * 256 + t];
    __syncthreads();
    for (int r = 0; r < 32; r++) {
        int j = jbase + warp * 32 + r;
        const float* w = W + (size_t)j * 256;
        float4 wa = *(const float4*)(w + 4 * lane);
        float4 wb = *(const float4*)(w + 128 + 4 * lane);
        float s[4];
#pragma unroll
        for (int cc = 0; cc < 4; cc++) {
            float4 xa = *(const float4*)(&shx[cc][4 * lane]);
            float4 xb = *(const float4*)(&shx[cc][128 + 4 * lane]);
            s[cc] = wa.x * xa.x + wa.y * xa.y + wa.z * xa.z + wa.w * xa.w
                  + wb.x * xb.x + wb.y * xb.y + wb.z * xb.z + wb.w * xb.w;
        }
#pragma unroll
        for (int off = 16; off > 0; off >>= 1)
#pragma unroll
            for (int cc = 0; cc < 4; cc++)
                s[cc] += __shfl_xor_sync(0xffffffffu, s[cc], off);
        if (lane == 0) {
            float bj = B[j];
#pragma unroll
            for (int cc = 0; cc < 4; cc++)
                g_qkvA[(cbase + cc) * 768 + j] = s[cc] + bj;
        }
    }
}

// ---------------- fused transformer layer ----------------
// 512 threads, 4 commits per CTA, grid 25.
// attn + out-proj + LN1 + ff1 + ff2 + LN2, then qkv-for-next-layer (lflag=0)
// or ranking head (lflag=1).
__global__ void __launch_bounds__(512) k_layer(
    const float* __restrict__ Wo, const float* __restrict__ Bo,
    const float* __restrict__ g1, const float* __restrict__ b1,
    const float* __restrict__ W1, const float* __restrict__ B1,
    const float* __restrict__ W2, const float* __restrict__ B2,
    const float* __restrict__ g2, const float* __restrict__ b2,
    int lflag,
    const float* __restrict__ Wn, const float* __restrict__ Bn,
    const float* __restrict__ r1w, const float* __restrict__ r1b,
    const float* __restrict__ r2w, const float* __restrict__ r2b,
    float* __restrict__ out) {
    int cbase = blockIdx.x * 4;
    int t = threadIdx.x, w = t >> 5, lane = t & 31;
    __shared__ __align__(16) float sq[4][256];    // q per commit
    __shared__ __align__(16) float shx[4][256];   // running x (residual)
    __shared__ __align__(16) float satt[4][256];
    __shared__ float sho[4][256];
    __shared__ __align__(16) float uni[4][1024];  // she (attn) then shff (ff1)
    __shared__ float shh[4][128];
    __shared__ float redS[4][4], redQ[4][4];

    const float* qin = lflag ? g_qkvB : g_qkvA;

    for (int i = t; i < 1024; i += 512) {
        int cc = i >> 8, k = i & 255;
        sq[cc][k]  = qin[(cbase + cc) * 768 + k];
        shx[cc][k] = g_x[(cbase + cc) * 256 + k];
    }
    __syncthreads();

    // ---- attention: warp -> (commit, head-pair) ----
    {
        int cc = w >> 2, hp = w & 3;
        const float scale = 0.17677669529663687f;
#pragma unroll
        for (int hh = 0; hh < 2; hh++) {
            int h = hp * 2 + hh;
            const float* qq = &sq[cc][h * 32];
            float sc[4];
#pragma unroll
            for (int r = 0; r < 4; r++) {
                int m = lane + 32 * r;
                if (m < CC) {
                    const float* kk = qin + m * 768 + 256 + h * 32;
                    float s = 0.f;
#pragma unroll
                    for (int kx = 0; kx < 8; kx++) {
                        float4 a = *(const float4*)(kk + 4 * kx);
                        float4 b = *(const float4*)(qq + 4 * kx);
                        s += a.x * b.x + a.y * b.y + a.z * b.z + a.w * b.w;
                    }
                    sc[r] = s * scale;
                } else sc[r] = -3.0e38f;
            }
            float M = fmaxf(fmaxf(sc[0], sc[1]), fmaxf(sc[2], sc[3]));
#pragma unroll
            for (int off = 16; off > 0; off >>= 1)
                M = fmaxf(M, __shfl_xor_sync(0xffffffffu, M, off));
            float sum = 0.f;
#pragma unroll
            for (int r = 0; r < 4; r++) {
                int m = lane + 32 * r;
                float e = (m < CC) ? __expf(sc[r] - M) : 0.f;
                if (m < CC) uni[cc][h * 128 + m] = e;
                sum += e;
            }
#pragma unroll
            for (int off = 16; off > 0; off >>= 1)
                sum += __shfl_xor_sync(0xffffffffu, sum, off);
            __syncwarp();
            float inv = 1.f / sum;
            float acc = 0.f;
#pragma unroll 4
            for (int m = 0; m < CC; m++)
                acc += uni[cc][h * 128 + m] * qin[m * 768 + 512 + h * 32 + lane];
            satt[cc][h * 32 + lane] = acc * inv;
        }
    }
    __syncthreads();

    // ---- output projection (256 rows, batched over 4 commits) ----
    for (int r = 0; r < 16; r++) {
        int j = w * 16 + r;
        const float* wp = Wo + (size_t)j * 256;
        float4 wa = *(const float4*)(wp + 4 * lane);
        float4 wb = *(const float4*)(wp + 128 + 4 * lane);
        float s[4];
#pragma unroll
        for (int cc = 0; cc < 4; cc++) {
            float4 xa = *(const float4*)(&satt[cc][4 * lane]);
            float4 xb = *(const float4*)(&satt[cc][128 + 4 * lane]);
            s[cc] = wa.x * xa.x + wa.y * xa.y + wa.z * xa.z + wa.w * xa.w
                  + wb.x * xb.x + wb.y * xb.y + wb.z * xb.z + wb.w * xb.w;
        }
#pragma unroll
        for (int off = 16; off > 0; off >>= 1)
#pragma unroll
            for (int cc = 0; cc < 4; cc++)
                s[cc] += __shfl_xor_sync(0xffffffffu, s[cc], off);
        if (lane == 0) {
            float bj = Bo[j];
#pragma unroll
            for (int cc = 0; cc < 4; cc++) sho[cc][j] = s[cc] + bj;
        }
    }
    __syncthreads();

    // ---- residual + LN1 (128 threads per commit, 2 elems per thread) ----
    {
        int g = t >> 7, lt = t & 127, wig = (t >> 5) & 3;
        float v0 = shx[g][lt] + sho[g][lt];
        float v1 = shx[g][lt + 128] + sho[g][lt + 128];
        float s = v0 + v1, q = v0 * v0 + v1 * v1;
#pragma unroll
        for (int off = 16; off > 0; off >>= 1) {
            s += __shfl_xor_sync(0xffffffffu, s, off);
            q += __shfl_xor_sync(0xffffffffu, q, off);
        }
        if (lane == 0) { redS[g][wig] = s; redQ[g][wig] = q; }
        __syncthreads();
        float S = redS[g][0] + redS[g][1] + redS[g][2] + redS[g][3];
        float Q = redQ[g][0] + redQ[g][1] + redQ[g][2] + redQ[g][3];
        float mu = S * (1.0f / 256.0f);
        float var = Q * (1.0f / 256.0f) - mu * mu;
        float inv = rsqrtf(var + 1e-5f);
        shx[g][lt]       = (v0 - mu) * inv * g1[lt] + b1[lt];
        shx[g][lt + 128] = (v1 - mu) * inv * g1[lt + 128] + b1[lt + 128];
    }
    __syncthreads();

    // ---- ff1 + gelu (1024 rows) ----
    for (int r = 0; r < 64; r++) {
        int j = w * 64 + r;
        const float* wp = W1 + (size_t)j * 256;
        float4 wa = *(const float4*)(wp + 4 * lane);
        float4 wb = *(const float4*)(wp + 128 + 4 * lane);
        float s[4];
#pragma unroll
        for (int cc = 0; cc < 4; cc++) {
            float4 xa = *(const float4*)(&shx[cc][4 * lane]);
            float4 xb = *(const float4*)(&shx[cc][128 + 4 * lane]);
            s[cc] = wa.x * xa.x + wa.y * xa.y + wa.z * xa.z + wa.w * xa.w
                  + wb.x * xb.x + wb.y * xb.y + wb.z * xb.z + wb.w * xb.w;
        }
#pragma unroll
        for (int off = 16; off > 0; off >>= 1)
#pragma unroll
            for (int cc = 0; cc < 4; cc++)
                s[cc] += __shfl_xor_sync(0xffffffffu, s[cc], off);
        if (lane == 0) {
            float bj = B1[j];
#pragma unroll
            for (int cc = 0; cc < 4; cc++)
                uni[cc][j] = gelu_exact(s[cc] + bj);
        }
    }
    __syncthreads();

    // ---- ff2 (256 rows, K=1024) ----
    for (int r = 0; r < 16; r++) {
        int j = w * 16 + r;
        const float4* wr = (const float4*)(W2 + (size_t)j * 1024);
        float4 wreg[8];
#pragma unroll
        for (int q8 = 0; q8 < 8; q8++) wreg[q8] = wr[q8 * 32 + lane];
        float s[4];
#pragma unroll
        for (int cc = 0; cc < 4; cc++) {
            float acc = 0.f;
#pragma unroll
            for (int q8 = 0; q8 < 8; q8++) {
                float4 x = *(const float4*)(&uni[cc][q8 * 128 + 4 * lane]);
                acc += wreg[q8].x * x.x + wreg[q8].y * x.y + wreg[q8].z * x.z + wreg[q8].w * x.w;
            }
            s[cc] = acc;
        }
#pragma unroll
        for (int off = 16; off > 0; off >>= 1)
#pragma unroll
            for (int cc = 0; cc < 4; cc++)
                s[cc] += __shfl_xor_sync(0xffffffffu, s[cc], off);
        if (lane == 0) {
            float bj = B2[j];
#pragma unroll
            for (int cc = 0; cc < 4; cc++) sho[cc][j] = s[cc] + bj;
        }
    }
    __syncthreads();

    // ---- residual + LN2 -> shx and g_x  (residual = post-LN1 x, i.e. shx!) ----
    {
        int g = t >> 7, lt = t & 127, wig = (t >> 5) & 3;
        float v0 = shx[g][lt] + sho[g][lt];            // FIX: was g_x (stale)
        float v1 = shx[g][lt + 128] + sho[g][lt + 128];
        float s = v0 + v1, q = v0 * v0 + v1 * v1;
#pragma unroll
        for (int off = 16; off > 0; off >>= 1) {
            s += __shfl_xor_sync(0xffffffffu, s, off);
            q += __shfl_xor_sync(0xffffffffu, q, off);
        }
        if (lane == 0) { redS[g][wig] = s; redQ[g][wig] = q; }
        __syncthreads();
        float S = redS[g][0] + redS[g][1] + redS[g][2] + redS[g][3];
        float Q = redQ[g][0] + redQ[g][1] + redQ[g][2] + redQ[g][3];
        float mu = S * (1.0f / 256.0f);
        float var = Q * (1.0f / 256.0f) - mu * mu;
        float inv = rsqrtf(var + 1e-5f);
        float n0 = (v0 - mu) * inv * g2[lt] + b2[lt];
        float n1 = (v1 - mu) * inv * g2[lt + 128] + b2[lt + 128];
        shx[g][lt] = n0; shx[g][lt + 128] = n1;
        g_x[(cbase + g) * 256 + lt] = n0;
        g_x[(cbase + g) * 256 + lt + 128] = n1;
    }
    __syncthreads();

    if (lflag == 0) {
        // ---- qkv for next layer -> g_qkvB ----
        for (int r = 0; r < 48; r++) {
            int j = w * 48 + r;
            const float* wp = Wn + (size_t)j * 256;
            float4 wa = *(const float4*)(wp + 4 * lane);
            float4 wb = *(const float4*)(wp + 128 + 4 * lane);
            float s[4];
#pragma unroll
            for (int cc = 0; cc < 4; cc++) {
                float4 xa = *(const float4*)(&shx[cc][4 * lane]);
                float4 xb = *(const float4*)(&shx[cc][128 + 4 * lane]);
                s[cc] = wa.x * xa.x + wa.y * xa.y + wa.z * xa.z + wa.w * xa.w
                      + wb.x * xb.x + wb.y * xb.y + wb.z * xb.z + wb.w * xb.w;
            }
#pragma unroll
            for (int off = 16; off > 0; off >>= 1)
#pragma unroll
                for (int cc = 0; cc < 4; cc++)
                    s[cc] += __shfl_xor_sync(0xffffffffu, s[cc], off);
            if (lane == 0) {
                float bj = Bn[j];
#pragma unroll
                for (int cc = 0; cc < 4; cc++)
                    g_qkvB[(cbase + cc) * 768 + j] = s[cc] + bj;
            }
        }
    } else {
        // ---- ranking head ----
        for (int r = 0; r < 8; r++) {
            int j = w * 8 + r;
            const float* wp = r1w + (size_t)j * 256;
            float4 wa = *(const float4*)(wp + 4 * lane);
            float4 wb = *(const float4*)(wp + 128 + 4 * lane);
            float s[4];
#pragma unroll
            for (int cc = 0; cc < 4; cc++) {
                float4 xa = *(const float4*)(&shx[cc][4 * lane]);
                float4 xb = *(const float4*)(&shx[cc][128 + 4 * lane]);
                s[cc] = wa.x * xa.x + wa.y * xa.y + wa.z * xa.z + wa.w * xa.w
                      + wb.x * xb.x + wb.y * xb.y + wb.z * xb.z + wb.w * xb.w;
            }
#pragma unroll
            for (int off = 16; off > 0; off >>= 1)
#pragma unroll
                for (int cc = 0; cc < 4; cc++)
                    s[cc] += __shfl_xor_sync(0xffffffffu, s[cc], off);
            if (lane == 0) {
                float bj = r1b[j];
#pragma unroll
                for (int cc = 0; cc < 4; cc++)
                    shh[cc][j] = gelu_exact(s[cc] + bj);
            }
        }
        __syncthreads();
        if (w < 4) {
            float s = 0.f;
#pragma unroll
            for (int r = 0; r < 4; r++)
                s += shh[w][lane + 32 * r] * r2w[lane + 32 * r];
#pragma unroll
            for (int off = 16; off > 0; off >>= 1)
                s += __shfl_xor_sync(0xffffffffu, s, off);
            if (lane == 0) out[cbase + w] = s + r2b[0];
        }
    }
}

// ---------------- launch ----------------
extern "C" void kernel_launch(void* const* d_in, const int* in_sizes, int n_in,
                              void* d_out, int out_size) {
    const float* x    = (const float*)d_in[0];
    const int*   ci   = (const int*)d_in[1];
    const float* q    = (const float*)d_in[3];
    const float* kw   = (const float*)d_in[4];
    const float* vw   = (const float*)d_in[6];
    const float* vb   = (const float*)d_in[7];
    const float* pw   = (const float*)d_in[8];
    const float* pb   = (const float*)d_in[9];
    const float* png  = (const float*)d_in[10];
    const float* pnb  = (const float*)d_in[11];
    const float* tinw = (const float*)d_in[12];
    const float* tinb = (const float*)d_in[13];
    const float* totw = (const float*)d_in[14];
    const float* totb = (const float*)d_in[15];
    const float* ln1g = (const float*)d_in[16];
    const float* ln1b = (const float*)d_in[17];
    const float* ff1w = (const float*)d_in[18];
    const float* ff1b = (const float*)d_in[19];
    const float* ff2w = (const float*)d_in[20];
    const float* ff2b = (const float*)d_in[21];
    const float* ln2g = (const float*)d_in[22];
    const float* ln2b = (const float*)d_in[23];
    const float* r1w  = (const float*)d_in[24];
    const float* r1b  = (const float*)d_in[25];
    const float* r2w  = (const float*)d_in[26];
    const float* r2b  = (const float*)d_in[27];
    float* out = (float*)d_out;
    int n = in_sizes[0] / HH;

    k_wqk_init<<<9, 256>>>(q, kw);            // launch 1
    k_hist<<<256, 256>>>(ci, n);              // launch 2
    k_scatter<<<256, 256>>>(ci, n);           // launch 3
    k_main<<<dim3(CC, BY), 128>>>(x);         // launch 4  (profiled)
    k_pool<<<CC, 256>>>(vw, vb, pw, pb, png, pnb);
    k_qkv<<<dim3(25, 3), 256>>>(tinw, tinb);  // layer-0 qkv -> g_qkvA
    // layer 0: reads g_qkvA, writes g_qkvB (qkv for layer 1)
    k_layer<<<25, 512>>>(totw, totb, ln1g, ln1b,
                         ff1w, ff1b, ff2w, ff2b, ln2g, ln2b,
                         0, tinw + (size_t)768 * 256, tinb + 768,
                         r1w, r1b, r2w, r2b, out);
    // layer 1: reads g_qkvB, writes head output
    k_layer<<<25, 512>>>(totw + (size_t)256 * 256, totb + 256,
                         ln1g + 256, ln1b + 256,
                         ff1w + (size_t)1024 * 256, ff1b + 1024,
                         ff2w + (size_t)256 * 1024, ff2b + 256,
                         ln2g + 256, ln2b + 256,
                         1, tinw, tinb,
                         r1w, r1b, r2w, r2b, out);
}

// round 13
// speedup vs baseline: 1.5573x; 1.4364x over previous
#include <cuda_runtime.h>
#include <math.h>

#define HH   256
#define NHH  8
#define CC   100
#define NMAX 262144
#define BY   18           // partial chunks per commit in k_main
#define TW   8            // nodes per shared tile in k_main

typedef unsigned long long ull;

// ---------------- device scratch ----------------
__device__ __align__(16) float g_wqk[NHH * HH];
__device__ int   g_counts[CC];
__device__ int   g_offsets[CC + 1];
__device__ int   g_cursor[CC];
__device__ int   g_sorted[NMAX];
__device__ __align__(16) float g_Apart[CC * BY * NHH * HH];   // ~14.7MB partials
__device__ float g_denpart[CC * BY * NHH];
__device__ __align__(16) float g_x[CC * HH];
__device__ __align__(16) float g_qkv[CC * 3 * HH];
__device__ __align__(16) float g_ff[CC * 4 * HH];

// ---------------- helpers ----------------
__device__ __forceinline__ ull fma2(ull a, ull b, ull c) {
    ull d;
    asm("fma.rn.f32x2 %0, %1, %2, %3;" : "=l"(d) : "l"(a), "l"(b), "l"(c));
    return d;
}
__device__ __forceinline__ void upk2(ull v, float& lo, float& hi) {
    asm("mov.b64 {%0, %1}, %2;" : "=f"(lo), "=f"(hi) : "l"(v));
}
__device__ __forceinline__ ull pk2(float lo, float hi) {
    ull r; asm("mov.b64 %0, {%1, %2};" : "=l"(r) : "f"(lo), "f"(hi)); return r;
}
__device__ __forceinline__ float gelu_exact(float v) {
    return 0.5f * v * (1.0f + erff(v * 0.70710678118654752f));
}

__device__ __forceinline__ float block_ln_256(float v, float gg, float bb, float* red) {
    int t = threadIdx.x, lane = t & 31, w = t >> 5;
    float s = v, q = v * v;
#pragma unroll
    for (int off = 16; off > 0; off >>= 1) {
        s += __shfl_xor_sync(0xffffffffu, s, off);
        q += __shfl_xor_sync(0xffffffffu, q, off);
    }
    if (lane == 0) { red[w] = s; red[8 + w] = q; }
    __syncthreads();
    float S = 0.f, Q = 0.f;
#pragma unroll
    for (int i = 0; i < 8; i++) { S += red[i]; Q += red[8 + i]; }
    float mu  = S * (1.0f / 256.0f);
    float var = Q * (1.0f / 256.0f) - mu * mu;
    return (v - mu) * rsqrtf(var + 1e-5f) * gg + bb;
}

// ---------------- setup ----------------
__global__ void k_wqk_init(const float* __restrict__ q, const float* __restrict__ kw) {
    if (blockIdx.x == 8) {
        int t = threadIdx.x;
        if (t < CC) { g_counts[t] = 0; g_cursor[t] = 0; }
        return;
    }
    const float scale = 0.17677669529663687f;
    int h = blockIdx.x, i = threadIdx.x;
    float acc = 0.f;
#pragma unroll 8
    for (int d = 0; d < 32; d++) acc += q[h * 32 + d] * kw[(h * 32 + d) * HH + i];
    g_wqk[h * HH + i] = acc * scale;
}

__global__ void __launch_bounds__(256) k_hist(const int* __restrict__ ci, int n) {
    __shared__ int sh[8][CC];
    int t = threadIdx.x, warp = t >> 5;
    for (int j = t; j < 8 * CC; j += 256) sh[j / CC][j % CC] = 0;
    __syncthreads();
    int n4 = n >> 2;
    const int4* ci4 = (const int4*)ci;
    for (int i = blockIdx.x * 256 + t; i < n4; i += gridDim.x * 256) {
        int4 v = ci4[i];
        atomicAdd(&sh[warp][v.x], 1);
        atomicAdd(&sh[warp][v.y], 1);
        atomicAdd(&sh[warp][v.z], 1);
        atomicAdd(&sh[warp][v.w], 1);
    }
    __syncthreads();
    for (int c = t; c < CC; c += 256) {
        int s = 0;
#pragma unroll
        for (int w = 0; w < 8; w++) s += sh[w][c];
        atomicAdd(&g_counts[c], s);
    }
}

__global__ void __launch_bounds__(256) k_scatter(const int* __restrict__ ci, int n) {
    __shared__ int soff[CC + 1], scnt[CC], sbase[CC], scur[CC];
    int t = threadIdx.x;
    for (int j = t; j < CC; j += 256) { scnt[j] = 0; scur[j] = 0; }
    __syncthreads();
    int per = ((n + gridDim.x - 1) / gridDim.x + 3) & ~3;
    int lo = blockIdx.x * per;
    int hi = min(n, lo + per);
    const int4* ci4 = (const int4*)ci;
    for (int i4 = (lo >> 2) + t; i4 < (hi >> 2); i4 += 256) {
        int4 v = ci4[i4];
        atomicAdd(&scnt[v.x], 1);
        atomicAdd(&scnt[v.y], 1);
        atomicAdd(&scnt[v.z], 1);
        atomicAdd(&scnt[v.w], 1);
    }
    __syncthreads();
    if (t == 0) {
        int s = 0;
        for (int c = 0; c < CC; c++) { soff[c] = s; s += g_counts[c]; }
        soff[CC] = s;
        if (blockIdx.x == 0)
            for (int c = 0; c <= CC; c++) g_offsets[c] = soff[c];
    }
    __syncthreads();
    if (t < CC) sbase[t] = soff[t] + atomicAdd(&g_cursor[t], scnt[t]);
    __syncthreads();
    for (int i = lo + t; i < hi; i += 256) {
        int c = ci[i];
        int p = sbase[c] + atomicAdd(&scur[c], 1);
        g_sorted[p] = i;
    }
}

// ---------------- main streaming pass ----------------
// CTA = 128 threads (4 warps). Warp w owns heads {2w, 2w+1}. Tiles of TW rows
// staged in shared (double buffered).
__global__ void __launch_bounds__(128) k_main(const float* __restrict__ X) {
    __shared__ __align__(16) float tile[2][TW * 256];
    int c = blockIdx.x;
    int t = threadIdx.x;
    int warp = t >> 5, lane = t & 31;
    int start = g_offsets[c], end = g_offsets[c + 1];
    int cnt = end - start;
    int chunk = (cnt + BY - 1) / BY;
    int mylo = start + blockIdx.y * chunk;
    int myhi = min(end, mylo + chunk);
    int nt = myhi - mylo;
    int ntiles = (nt + TW - 1) / TW;

    int h0 = warp * 2;
    ull w2[2][4];
#pragma unroll
    for (int hh = 0; hh < 2; hh++)
#pragma unroll
        for (int k = 0; k < 4; k++)
            w2[hh][k] = *(const ull*)(g_wqk + (h0 + hh) * 256 + k * 64 + 2 * lane);
    ull a2[2][4];
#pragma unroll
    for (int hh = 0; hh < 2; hh++)
#pragma unroll
        for (int k = 0; k < 4; k++) a2[hh][k] = 0ull;
    float dacc[2] = {0.f, 0.f};

    int lr = t >> 4, sub = t & 15;   // load role: 16 threads per row

    if (nt > 0) {
        {
            int p = mylo + lr;
            int node = (p < myhi) ? g_sorted[p] : g_sorted[mylo];
            const float4* src = (const float4*)(X + (size_t)node * 256);
            float4* dst = (float4*)(&tile[0][lr * 256]);
            dst[sub]      = __ldcs(src + sub);
            dst[sub + 16] = __ldcs(src + sub + 16);
            dst[sub + 32] = __ldcs(src + sub + 32);
            dst[sub + 48] = __ldcs(src + sub + 48);
        }
        int buf = 0;
        for (int j = 0; j < ntiles; j++) {
            __syncthreads();
            if (j + 1 < ntiles) {
                int p = mylo + (j + 1) * TW + lr;
                int node = (p < myhi) ? g_sorted[p] : g_sorted[mylo];
                const float4* src = (const float4*)(X + (size_t)node * 256);
                float4* dst = (float4*)(&tile[buf ^ 1][lr * 256]);
                dst[sub]      = __ldcs(src + sub);
                dst[sub + 16] = __ldcs(src + sub + 16);
                dst[sub + 32] = __ldcs(src + sub + 32);
                dst[sub + 48] = __ldcs(src + sub + 48);
            }
            int rmax = min(TW, nt - j * TW);
            const float* tb = tile[buf];
            for (int rr = 0; rr < rmax; rr++) {
                const float* row = tb + rr * 256;
                ull x0 = *(const ull*)(row + 2 * lane);
                ull x1 = *(const ull*)(row + 64 + 2 * lane);
                ull x2 = *(const ull*)(row + 128 + 2 * lane);
                ull x3 = *(const ull*)(row + 192 + 2 * lane);
                float p0, p1;
                {
                    ull acc = fma2(x0, w2[0][0], 0ull);
                    acc = fma2(x1, w2[0][1], acc);
                    acc = fma2(x2, w2[0][2], acc);
                    acc = fma2(x3, w2[0][3], acc);
                    float lo, hi; upk2(acc, lo, hi); p0 = lo + hi;
                }
                {
                    ull acc = fma2(x0, w2[1][0], 0ull);
                    acc = fma2(x1, w2[1][1], acc);
                    acc = fma2(x2, w2[1][2], acc);
                    acc = fma2(x3, w2[1][3], acc);
                    float lo, hi; upk2(acc, lo, hi); p1 = lo + hi;
                }
#pragma unroll
                for (int off = 16; off > 0; off >>= 1) {
                    p0 += __shfl_xor_sync(0xffffffffu, p0, off);
                    p1 += __shfl_xor_sync(0xffffffffu, p1, off);
                }
                float e0 = __expf(p0), e1 = __expf(p1);
                dacc[0] += e0; dacc[1] += e1;
                ull e02 = pk2(e0, e0), e12 = pk2(e1, e1);
                a2[0][0] = fma2(e02, x0, a2[0][0]);
                a2[0][1] = fma2(e02, x1, a2[0][1]);
                a2[0][2] = fma2(e02, x2, a2[0][2]);
                a2[0][3] = fma2(e02, x3, a2[0][3]);
                a2[1][0] = fma2(e12, x0, a2[1][0]);
                a2[1][1] = fma2(e12, x1, a2[1][1]);
                a2[1][2] = fma2(e12, x2, a2[1][2]);
                a2[1][3] = fma2(e12, x3, a2[1][3]);
            }
            buf ^= 1;
        }
    }
    ull* base = (ull*)(g_Apart + (size_t)(c * BY + blockIdx.y) * 2048);
#pragma unroll
    for (int hh = 0; hh < 2; hh++)
#pragma unroll
        for (int k = 0; k < 4; k++)
            base[(h0 + hh) * 128 + k * 32 + lane] = a2[hh][k];
    if (lane == 0) {
        g_denpart[(c * BY + blockIdx.y) * 8 + h0]     = dacc[0];
        g_denpart[(c * BY + blockIdx.y) * 8 + h0 + 1] = dacc[1];
    }
}

// ---------------- pooling epilogue ----------------
__global__ void __launch_bounds__(256) k_pool(const float* __restrict__ vw,
                                              const float* __restrict__ vb,
                                              const float* __restrict__ pw,
                                              const float* __restrict__ pb,
                                              const float* __restrict__ png,
                                              const float* __restrict__ pnb) {
    int c = blockIdx.x, t = threadIdx.x, warp = t >> 5, lane = t & 31;
    __shared__ __align__(16) float shA[2048];
    __shared__ __align__(16) float shP[256];
    __shared__ float shO[256];
    __shared__ float shden[8];
    __shared__ float red[16];
#pragma unroll
    for (int j = 0; j < 8; j++) {
        float s = 0.f;
#pragma unroll
        for (int p = 0; p < BY; p++)
            s += g_Apart[(size_t)(c * BY + p) * 2048 + t + 256 * j];
        shA[t + 256 * j] = s;
    }
    if (t < 8) {
        float d = 0.f;
#pragma unroll
        for (int p = 0; p < BY; p++) d += g_denpart[(c * BY + p) * 8 + t];
        shden[t] = d;
    }
    __syncthreads();
    int h = warp;
    float den = shden[h];
    float rden = den > 0.f ? 1.f / den : 0.f;
    for (int d = 0; d < 32; d++) {
        const float* w = vw + (h * 32 + d) * 256;
        float4 wa = *(const float4*)(w + 4 * lane);
        float4 wb = *(const float4*)(w + 128 + 4 * lane);
        float4 xa = *(const float4*)(shA + h * 256 + 4 * lane);
        float4 xb = *(const float4*)(shA + h * 256 + 128 + 4 * lane);
        float s = wa.x * xa.x + wa.y * xa.y + wa.z * xa.z + wa.w * xa.w
                + wb.x * xb.x + wb.y * xb.y + wb.z * xb.z + wb.w * xb.w;
#pragma unroll
        for (int off = 16; off > 0; off >>= 1) s += __shfl_xor_sync(0xffffffffu, s, off);
        if (lane == 0)
            shP[h * 32 + d] = (den > 0.f) ? (s * rden + vb[h * 32 + d]) : 0.f;
    }
    __syncthreads();
    for (int d = 0; d < 32; d++) {
        int j = warp * 32 + d;
        const float* w = pw + j * 256;
        float4 wa = *(const float4*)(w + 4 * lane);
        float4 wb = *(const float4*)(w + 128 + 4 * lane);
        float4 xa = *(const float4*)(shP + 4 * lane);
        float4 xb = *(const float4*)(shP + 128 + 4 * lane);
        float s = wa.x * xa.x + wa.y * xa.y + wa.z * xa.z + wa.w * xa.w
                + wb.x * xb.x + wb.y * xb.y + wb.z * xb.z + wb.w * xb.w;
#pragma unroll
        for (int off = 16; off > 0; off >>= 1) s += __shfl_xor_sync(0xffffffffu, s, off);
        if (lane == 0) shO[j] = s + pb[j];
    }
    __syncthreads();
    float r = block_ln_256(shO[t], png[t], pnb[t], red);
    g_x[c * 256 + t] = (g_counts[c] > 0) ? r : 0.f;
}

// qkv projection: 4 commits per block, 128-row slice per blockIdx.y (6 slices).
__global__ void __launch_bounds__(256) k_qkv(const float* __restrict__ W,
                                             const float* __restrict__ B) {
    int cbase = blockIdx.x * 4, t = threadIdx.x, warp = t >> 5, lane = t & 31;
    int jbase = blockIdx.y * 128;
    __shared__ __align__(16) float shx[4][256];
#pragma unroll
    for (int cc = 0; cc < 4; cc++)
        shx[cc][t] = g_x[(cbase + cc) * 256 + t];
    __syncthreads();
    for (int r = 0; r < 16; r++) {
        int j = jbase + warp * 16 + r;
        const float* w = W + (size_t)j * 256;
        float4 wa = *(const float4*)(w + 4 * lane);
        float4 wb = *(const float4*)(w + 128 + 4 * lane);
        float s[4];
#pragma unroll
        for (int cc = 0; cc < 4; cc++) {
            float4 xa = *(const float4*)(&shx[cc][4 * lane]);
            float4 xb = *(const float4*)(&shx[cc][128 + 4 * lane]);
            s[cc] = wa.x * xa.x + wa.y * xa.y + wa.z * xa.z + wa.w * xa.w
                  + wb.x * xb.x + wb.y * xb.y + wb.z * xb.z + wb.w * xb.w;
        }
#pragma unroll
        for (int off = 16; off > 0; off >>= 1)
#pragma unroll
            for (int cc = 0; cc < 4; cc++)
                s[cc] += __shfl_xor_sync(0xffffffffu, s[cc], off);
        if (lane == 0) {
            float bj = B[j];
#pragma unroll
            for (int cc = 0; cc < 4; cc++)
                g_qkv[(cbase + cc) * 768 + j] = s[cc] + bj;
        }
    }
}

// attention + output projection + residual + LN1, per-commit (grid 100).
__global__ void __launch_bounds__(256) k_attn_oln(const float* __restrict__ W,
                                                  const float* __restrict__ B,
                                                  const float* __restrict__ gg,
                                                  const float* __restrict__ bb) {
    int c = blockIdx.x, t = threadIdx.x, h = t >> 5, lane = t & 31;
    __shared__ __align__(16) float shq[256];
    __shared__ float she[8][128];
    __shared__ float satt[256];
    __shared__ float sho[256];
    __shared__ float red[16];
    shq[t] = g_qkv[c * 768 + t];
    __syncthreads();
    const float scale = 0.17677669529663687f;
    float sc[4];
#pragma unroll
    for (int r = 0; r < 4; r++) {
        int m = lane + 32 * r;
        if (m < CC) {
            const float* kk = g_qkv + m * 768 + 256 + h * 32;
            const float* qq = shq + h * 32;
            float s = 0.f;
#pragma unroll
            for (int kx = 0; kx < 8; kx++) {
                float4 a = *(const float4*)(kk + 4 * kx);
                float4 b = *(const float4*)(qq + 4 * kx);
                s += a.x * b.x + a.y * b.y + a.z * b.z + a.w * b.w;
            }
            sc[r] = s * scale;
        } else sc[r] = -3.0e38f;
    }
    float M = fmaxf(fmaxf(sc[0], sc[1]), fmaxf(sc[2], sc[3]));
#pragma unroll
    for (int off = 16; off > 0; off >>= 1) M = fmaxf(M, __shfl_xor_sync(0xffffffffu, M, off));
    float sum = 0.f;
#pragma unroll
    for (int r = 0; r < 4; r++) {
        int m = lane + 32 * r;
        float e = (m < CC) ? __expf(sc[r] - M) : 0.f;
        if (m < CC) she[h][m] = e;
        sum += e;
    }
#pragma unroll
    for (int off = 16; off > 0; off >>= 1) sum += __shfl_xor_sync(0xffffffffu, sum, off);
    __syncwarp();
    float inv = 1.f / sum;
    float acc = 0.f;
#pragma unroll 4
    for (int m = 0; m < CC; m++)
        acc += she[h][m] * g_qkv[m * 768 + 512 + h * 32 + lane];
    satt[h * 32 + lane] = acc * inv;
    __syncthreads();
    for (int d = 0; d < 32; d++) {
        int j = h * 32 + d;
        const float* w = W + (size_t)j * 256;
        float4 wa = *(const float4*)(w + 4 * lane);
        float4 wb = *(const float4*)(w + 128 + 4 * lane);
        float4 xa = *(const float4*)(satt + 4 * lane);
        float4 xb = *(const float4*)(satt + 128 + 4 * lane);
        float s = wa.x * xa.x + wa.y * xa.y + wa.z * xa.z + wa.w * xa.w
                + wb.x * xb.x + wb.y * xb.y + wb.z * xb.z + wb.w * xb.w;
#pragma unroll
        for (int off = 16; off > 0; off >>= 1) s += __shfl_xor_sync(0xffffffffu, s, off);
        if (lane == 0) sho[j] = s;
    }
    __syncthreads();
    float v = g_x[c * 256 + t] + sho[t] + B[t];
    float r = block_ln_256(v, gg[t], bb[t], red);
    g_x[c * 256 + t] = r;
}

// ff1 + gelu: 4 commits per block, 128-row slice per blockIdx.y (8 slices).
__global__ void __launch_bounds__(256) k_ff1(const float* __restrict__ W,
                                             const float* __restrict__ B) {
    int cbase = blockIdx.x * 4, t = threadIdx.x, warp = t >> 5, lane = t & 31;
    int jbase = blockIdx.y * 128;
    __shared__ __align__(16) float shx[4][256];
#pragma unroll
    for (int cc = 0; cc < 4; cc++)
        shx[cc][t] = g_x[(cbase + cc) * 256 + t];
    __syncthreads();
    for (int r = 0; r < 16; r++) {
        int j = jbase + warp * 16 + r;
        const float* w = W + (size_t)j * 256;
        float4 wa = *(const float4*)(w + 4 * lane);
        float4 wb = *(const float4*)(w + 128 + 4 * lane);
        float s[4];
#pragma unroll
        for (int cc = 0; cc < 4; cc++) {
            float4 xa = *(const float4*)(&shx[cc][4 * lane]);
            float4 xb = *(const float4*)(&shx[cc][128 + 4 * lane]);
            s[cc] = wa.x * xa.x + wa.y * xa.y + wa.z * xa.z + wa.w * xa.w
                  + wb.x * xb.x + wb.y * xb.y + wb.z * xb.z + wb.w * xb.w;
        }
#pragma unroll
        for (int off = 16; off > 0; off >>= 1)
#pragma unroll
            for (int cc = 0; cc < 4; cc++)
                s[cc] += __shfl_xor_sync(0xffffffffu, s[cc], off);
        if (lane == 0) {
            float bj = B[j];
#pragma unroll
            for (int cc = 0; cc < 4; cc++)
                g_ff[(cbase + cc) * 1024 + j] = gelu_exact(s[cc] + bj);
        }
    }
}

// ff2 + residual + LN2, ONE commit per CTA (grid 100); fused head on final layer.
__global__ void __launch_bounds__(256) k_ff2(const float* __restrict__ W,
                                             const float* __restrict__ B,
                                             const float* __restrict__ gg,
                                             const float* __restrict__ bb,
                                             int final_layer,
                                             const float* __restrict__ r1w,
                                             const float* __restrict__ r1b,
                                             const float* __restrict__ r2w,
                                             const float* __restrict__ r2b,
                                             float* __restrict__ out) {
    int c = blockIdx.x, t = threadIdx.x, warp = t >> 5, lane = t & 31;
    __shared__ __align__(16) float shf[1024];
    __shared__ float sho[256];
    __shared__ float red[16];
    __shared__ __align__(16) float shx[256];
    __shared__ float shh[128];
#pragma unroll
    for (int j = 0; j < 4; j++)
        shf[t + 256 * j] = g_ff[c * 1024 + t + 256 * j];
    __syncthreads();
    for (int r = 0; r < 32; r++) {
        int j = warp * 32 + r;
        const float4* wr = (const float4*)(W + (size_t)j * 1024);
        float acc = 0.f;
#pragma unroll
        for (int q8 = 0; q8 < 8; q8++) {
            float4 wv = wr[q8 * 32 + lane];
            float4 x = *(const float4*)(&shf[q8 * 128 + 4 * lane]);
            acc += wv.x * x.x + wv.y * x.y + wv.z * x.z + wv.w * x.w;
        }
#pragma unroll
        for (int off = 16; off > 0; off >>= 1) acc += __shfl_xor_sync(0xffffffffu, acc, off);
        if (lane == 0) sho[j] = acc + B[j];
    }
    __syncthreads();
    float v = g_x[c * 256 + t] + sho[t];
    float r = block_ln_256(v, gg[t], bb[t], red);
    if (!final_layer) { g_x[c * 256 + t] = r; return; }
    shx[t] = r;
    __syncthreads();

    // ---- fused ranking head ----
    for (int rr = 0; rr < 16; rr++) {
        int j = warp * 16 + rr;
        const float* w = r1w + (size_t)j * 256;
        float4 wa = *(const float4*)(w + 4 * lane);
        float4 wb = *(const float4*)(w + 128 + 4 * lane);
        float4 xa = *(const float4*)(&shx[4 * lane]);
        float4 xb = *(const float4*)(&shx[128 + 4 * lane]);
        float s = wa.x * xa.x + wa.y * xa.y + wa.z * xa.z + wa.w * xa.w
                + wb.x * xb.x + wb.y * xb.y + wb.z * xb.z + wb.w * xb.w;
#pragma unroll
        for (int off = 16; off > 0; off >>= 1) s += __shfl_xor_sync(0xffffffffu, s, off);
        if (lane == 0) shh[j] = gelu_exact(s + r1b[j]);
    }
    __syncthreads();
    if (warp == 0) {
        float s = 0.f;
#pragma unroll
        for (int rr = 0; rr < 4; rr++)
            s += shh[lane + 32 * rr] * r2w[lane + 32 * rr];
#pragma unroll
        for (int off = 16; off > 0; off >>= 1) s += __shfl_xor_sync(0xffffffffu, s, off);
        if (lane == 0) out[c] = s + r2b[0];
    }
}

// ---------------- launch ----------------
extern "C" void kernel_launch(void* const* d_in, const int* in_sizes, int n_in,
                              void* d_out, int out_size) {
    const float* x    = (const float*)d_in[0];
    const int*   ci   = (const int*)d_in[1];
    const float* q    = (const float*)d_in[3];
    const float* kw   = (const float*)d_in[4];
    const float* vw   = (const float*)d_in[6];
    const float* vb   = (const float*)d_in[7];
    const float* pw   = (const float*)d_in[8];
    const float* pb   = (const float*)d_in[9];
    const float* png  = (const float*)d_in[10];
    const float* pnb  = (const float*)d_in[11];
    const float* tinw = (const float*)d_in[12];
    const float* tinb = (const float*)d_in[13];
    const float* totw = (const float*)d_in[14];
    const float* totb = (const float*)d_in[15];
    const float* ln1g = (const float*)d_in[16];
    const float* ln1b = (const float*)d_in[17];
    const float* ff1w = (const float*)d_in[18];
    const float* ff1b = (const float*)d_in[19];
    const float* ff2w = (const float*)d_in[20];
    const float* ff2b = (const float*)d_in[21];
    const float* ln2g = (const float*)d_in[22];
    const float* ln2b = (const float*)d_in[23];
    const float* r1w  = (const float*)d_in[24];
    const float* r1b  = (const float*)d_in[25];
    const float* r2w  = (const float*)d_in[26];
    const float* r2b  = (const float*)d_in[27];
    float* out = (float*)d_out;
    int n = in_sizes[0] / HH;

    k_wqk_init<<<9, 256>>>(q, kw);            // launch 1
    k_hist<<<256, 256>>>(ci, n);              // launch 2
    k_scatter<<<256, 256>>>(ci, n);           // launch 3
    k_main<<<dim3(CC, BY), 128>>>(x);         // launch 4  (profiled)
    k_pool<<<CC, 256>>>(vw, vb, pw, pb, png, pnb);
    for (int l = 0; l < 2; l++) {
        k_qkv<<<dim3(25, 6), 256>>>(tinw + (size_t)l * 768 * 256, tinb + l * 768);
        k_attn_oln<<<CC, 256>>>(totw + (size_t)l * 256 * 256, totb + l * 256,
                                ln1g + l * 256, ln1b + l * 256);
        k_ff1<<<dim3(25, 8), 256>>>(ff1w + (size_t)l * 1024 * 256, ff1b + l * 1024);
        k_ff2<<<CC, 256>>>(ff2w + (size_t)l * 256 * 1024, ff2b + l * 256,
                           ln2g + l * 256, ln2b + l * 256,
                           (l == 1) ? 1 : 0, r1w, r1b, r2w, r2b, out);
    }
}